// round 11
// baseline (speedup 1.0000x reference)
#include <cuda_runtime.h>
#include <cuda_bf16.h>
#include <cstdint>

#define BB 8
#define CC 64
#define HWSZ (152 * 272)     // 41344
#define KK 500
#define KPAD 512
#define NSLOTS 32
#define NLBLK 512            // 8x8 tiles x 8 batches

#define ALPHA 0.25f
#define PROB_MIN 1e-4f

// Scratch (no allocations allowed)
__device__ __align__(16) __nv_bfloat16 g_curb[BB * KPAD * CC];
__device__ __align__(16) __nv_bfloat16 g_preb[BB * KPAD * CC];
__device__ double   g_accs[NSLOTS];   // zero-init; last block resets
__device__ unsigned g_count = 0;

__device__ __forceinline__ void mma_16816(float* c, const uint32_t* a,
                                          const uint32_t* b) {
    asm volatile(
        "mma.sync.aligned.m16n8k16.row.col.f32.bf16.bf16.f32 "
        "{%0,%1,%2,%3}, {%4,%5,%6,%7}, {%8,%9}, {%0,%1,%2,%3};"
        : "+f"(c[0]), "+f"(c[1]), "+f"(c[2]), "+f"(c[3])
        : "r"(a[0]), "r"(a[1]), "r"(a[2]), "r"(a[3]), "r"(b[0]), "r"(b[1]));
}

__device__ __forceinline__ float loss_fast(float x) {
    float e   = __expf(x);
    float r   = __fdividef(1.0f, 1.0f + e);   // 1 - sigmoid(x)
    float p   = fmaxf(r, PROB_MIN);
    float omp = 1.0f - p;
    return -(1.0f - ALPHA) * omp * omp * __logf(p);
}
__device__ __forceinline__ float loss_gen(float x, bool gt) {
    float e   = __expf(x);
    float r   = __fdividef(1.0f, 1.0f + e);
    float p   = gt ? (1.0f - r) : r;
    p = fmaxf(p, PROB_MIN);
    float a   = gt ? ALPHA : (1.0f - ALPHA);
    float omp = 1.0f - p;
    return -a * omp * omp * __logf(p);
}

// ---------------------------------------------------------------------------
// Gather + bf16 convert (identical to the proven round-7 version).
// ---------------------------------------------------------------------------
__global__ __launch_bounds__(256)
void gather_kernel(const float* __restrict__ cur_reid,
                   const float* __restrict__ pre_reid,
                   const void*  __restrict__ cur_inds,
                   const void*  __restrict__ pre_inds,
                   const void*  __restrict__ cur_cir,
                   const void*  __restrict__ pre_cir,
                   const int*   __restrict__ mask)
{
    __shared__ int s64;
    if (threadIdx.x < 32) {
        long long v = ((const long long*)cur_inds)[threadIdx.x];
        unsigned bad = __ballot_sync(0xffffffffu,
                                     (v < 0) || (v >= (long long)HWSZ));
        if (threadIdx.x == 0) s64 = (bad == 0);
    }
    __syncthreads();

    int tid = blockIdx.x * 256 + threadIdx.x;
    if (tid >= BB * KPAD * 16) return;
    int c4  = tid & 15;
    int bk  = tid >> 4;
    int b   = bk >> 9;
    int row = bk & (KPAD - 1);

    uint2* dstC = (uint2*)g_curb;
    uint2* dstP = (uint2*)g_preb;

    if (row >= KK) {
        uint2 z = make_uint2(0u, 0u);
        dstC[tid] = z;
        dstP[tid] = z;
        return;
    }
    int mk = b * KK + row;
    int m  = mask[mk];
    int ic, ip;
    if (s64) {
        ic = (int)(m ? ((const long long*)cur_inds)[mk]
                     : ((const long long*)cur_cir)[mk]);
        ip = (int)(m ? ((const long long*)pre_inds)[mk]
                     : ((const long long*)pre_cir)[mk]);
    } else {
        ic = m ? ((const int*)cur_inds)[mk] : ((const int*)cur_cir)[mk];
        ip = m ? ((const int*)pre_inds)[mk] : ((const int*)pre_cir)[mk];
    }
    size_t base = ((size_t)b * CC + 4 * c4) * (size_t)HWSZ;
    float c0 = cur_reid[base + ic];
    float c1 = cur_reid[base + HWSZ + ic];
    float c2 = cur_reid[base + 2 * (size_t)HWSZ + ic];
    float c3 = cur_reid[base + 3 * (size_t)HWSZ + ic];
    float p0 = pre_reid[base + ip];
    float p1 = pre_reid[base + HWSZ + ip];
    float p2 = pre_reid[base + 2 * (size_t)HWSZ + ip];
    float p3 = pre_reid[base + 3 * (size_t)HWSZ + ip];
    __nv_bfloat162 vc0, vc1, vp0, vp1;
    vc0.x = __float2bfloat16(c0); vc0.y = __float2bfloat16(c1);
    vc1.x = __float2bfloat16(c2); vc1.y = __float2bfloat16(c3);
    vp0.x = __float2bfloat16(p0); vp0.y = __float2bfloat16(p1);
    vp1.x = __float2bfloat16(p2); vp1.y = __float2bfloat16(p3);
    uint2 uc, up;
    uc.x = *(uint32_t*)&vc0; uc.y = *(uint32_t*)&vc1;
    up.x = *(uint32_t*)&vp0; up.y = *(uint32_t*)&vp1;
    dstC[tid] = uc;
    dstP[tid] = up;
}

// ---------------------------------------------------------------------------
// HMMA loss kernel, NO shared memory: every mma.sync fragment register is a
// contiguous 4B bf16-pair in the K-major gathered buffers, loaded directly
// with LDG.32 (L2-resident). No staging, no __syncthreads, no LDSM.
// Grid (8,8,8)=512 blocks, 8 warps of 32x16 warp tiles.
// Fragment mapping (verified against the ldmatrix-based round-5 kernel):
//   a0=(row gid,     k 2tig..+1)  a1=(row gid+8, k 2tig)
//   a2=(row gid,     k 2tig+8)    a3=(row gid+8, k 2tig+8)
//   b0=(n-row gid,   k 2tig..+1)  b1=(n-row gid, k 2tig+8)
// ---------------------------------------------------------------------------
__global__ __launch_bounds__(256)
void loss_kernel(const int* __restrict__ mask, float* __restrict__ out)
{
    __shared__ float wsum[8];

    int t   = threadIdx.x;
    int w   = t >> 5;
    int lid = t & 31;
    int b   = blockIdx.z;
    int it  = blockIdx.y;
    int jt  = blockIdx.x;
    int i0  = it * 64;
    int j0  = jt * 64;

    int wm  = w & 1;        // 2 x 32 rows
    int wn  = w >> 1;       // 4 x 16 cols
    int gid = lid >> 2;
    int tig = lid & 3;

    const uint32_t* A32 = (const uint32_t*)g_curb;   // row stride = 32 u32
    const uint32_t* B32 = (const uint32_t*)g_preb;

    int rowA = b * KPAD + i0 + wm * 32 + gid;        // fragment base rows
    int rowB = b * KPAD + j0 + wn * 16 + gid;

    float acc[2][2][4] = {};
    #pragma unroll
    for (int ks = 0; ks < 4; ks++) {
        int kb = ks * 8 + tig;                       // b32 offset within row
        uint32_t a[2][4];
        #pragma unroll
        for (int fm = 0; fm < 2; fm++) {
            const uint32_t* p = A32 + ((rowA + fm * 16) << 5) + kb;
            a[fm][0] = p[0];
            a[fm][1] = p[8 << 5];                    // +8 rows
            a[fm][2] = p[4];                         // +8 k (4 u32)
            a[fm][3] = p[(8 << 5) + 4];
        }
        uint32_t bf[2][2];
        #pragma unroll
        for (int fn = 0; fn < 2; fn++) {
            const uint32_t* q = B32 + ((rowB + fn * 8) << 5) + kb;
            bf[fn][0] = q[0];
            bf[fn][1] = q[4];
        }
        #pragma unroll
        for (int fm = 0; fm < 2; fm++)
            #pragma unroll
            for (int fn = 0; fn < 2; fn++)
                mma_16816(acc[fm][fn], a[fm], bf[fn]);
    }

    // Epilogue on fragments: c0:(i,j) c1:(i,j+1) c2:(i+8,j) c3:(i+8,j+1)
    float lsum = 0.0f;
    bool interior = (it < 7) && (jt < 7);
    bool diag     = (it == jt);

    if (interior && !diag) {
        #pragma unroll
        for (int fm = 0; fm < 2; fm++)
            #pragma unroll
            for (int fn = 0; fn < 2; fn++)
                #pragma unroll
                for (int rg = 0; rg < 4; rg++)
                    lsum += loss_fast(acc[fm][fn][rg]);
    } else {
        #pragma unroll
        for (int fm = 0; fm < 2; fm++) {
            int ib = i0 + wm * 32 + fm * 16 + gid;
            int m0 = (diag && ib     < KK) ? mask[b * KK + ib]     : 0;
            int m8 = (diag && ib + 8 < KK) ? mask[b * KK + ib + 8] : 0;
            #pragma unroll
            for (int fn = 0; fn < 2; fn++) {
                int jb = j0 + wn * 16 + fn * 8 + 2 * tig;
                #pragma unroll
                for (int rg = 0; rg < 4; rg++) {
                    int i = ib + (rg >> 1) * 8;
                    int j = jb + (rg & 1);
                    if (i < KK && j < KK) {
                        bool gt = diag && (i == j) &&
                                  (((rg >> 1) ? m8 : m0) != 0);
                        lsum += loss_gen(acc[fm][fn][rg], gt);
                    }
                }
            }
        }
    }

    // Reduce + last-block finalize
    #pragma unroll
    for (int o = 16; o > 0; o >>= 1)
        lsum += __shfl_xor_sync(0xffffffffu, lsum, o);
    if (lid == 0) wsum[w] = lsum;
    __syncthreads();

    if (t == 0) {
        float v = 0.f;
        #pragma unroll
        for (int k = 0; k < 8; k++) v += wsum[k];
        int bid = blockIdx.x + 8 * (blockIdx.y + 8 * blockIdx.z);
        atomicAdd(&g_accs[bid & (NSLOTS - 1)], (double)v);
        __threadfence();
        unsigned old = atomicAdd(&g_count, 1u);
        if (old == NLBLK - 1) {           // last block: finalize + reset
            double tot = 0.0;
            #pragma unroll
            for (int s = 0; s < NSLOTS; s++) {
                tot += g_accs[s];
                g_accs[s] = 0.0;
            }
            out[0] = (float)(tot / ((double)BB * KK * KK));
            __threadfence();
            g_count = 0u;
        }
    }
}

extern "C" void kernel_launch(void* const* d_in, const int* in_sizes, int n_in,
                              void* d_out, int out_size)
{
    const float* cur_reid = (const float*)d_in[0];
    const float* pre_reid = (const float*)d_in[1];
    const int*   mask     = (const int*)d_in[6];
    float* out = (float*)d_out;

    int totalGroups = BB * KPAD * 16;
    gather_kernel<<<(totalGroups + 255) / 256, 256>>>(cur_reid, pre_reid,
                                                      d_in[2], d_in[3],
                                                      d_in[4], d_in[5], mask);

    dim3 grid(8, 8, BB);
    loss_kernel<<<grid, 256>>>(mask, out);
}

// round 12
// speedup vs baseline: 1.2576x; 1.2576x over previous
#include <cuda_runtime.h>
#include <cuda_bf16.h>
#include <cstdint>

#define BB 8
#define CC 64
#define HWSZ (152 * 272)     // 41344
#define KK 500
#define KPAD 512
#define NSLOTS 32
#define NLBLK 512            // 8x8 tiles x 8 batches

#define ALPHA 0.25f
#define PROB_MIN 1e-4f

// Scratch (no allocations allowed)
__device__ __align__(16) __nv_bfloat16 g_curb[BB * KPAD * CC];
__device__ __align__(16) __nv_bfloat16 g_preb[BB * KPAD * CC];
__device__ double   g_accs[NSLOTS];   // zero-init; last block resets
__device__ unsigned g_count = 0;

__device__ __forceinline__ uint32_t smem_u32(const void* p) {
    uint32_t a;
    asm("{ .reg .u64 t; cvta.to.shared.u64 t, %1; cvt.u32.u64 %0, t; }"
        : "=r"(a) : "l"(p));
    return a;
}
__device__ __forceinline__ void ldsm_x4(uint32_t& r0, uint32_t& r1,
                                        uint32_t& r2, uint32_t& r3,
                                        uint32_t addr) {
    asm volatile("ldmatrix.sync.aligned.m8n8.x4.shared.b16 {%0,%1,%2,%3}, [%4];"
                 : "=r"(r0), "=r"(r1), "=r"(r2), "=r"(r3) : "r"(addr));
}
__device__ __forceinline__ void mma_16816(float* c, const uint32_t* a,
                                          const uint32_t* b) {
    asm volatile(
        "mma.sync.aligned.m16n8k16.row.col.f32.bf16.bf16.f32 "
        "{%0,%1,%2,%3}, {%4,%5,%6,%7}, {%8,%9}, {%0,%1,%2,%3};"
        : "+f"(c[0]), "+f"(c[1]), "+f"(c[2]), "+f"(c[3])
        : "r"(a[0]), "r"(a[1]), "r"(a[2]), "r"(a[3]), "r"(b[0]), "r"(b[1]));
}

__device__ __forceinline__ float loss_fast(float x) {
    float e   = __expf(x);
    float r   = __fdividef(1.0f, 1.0f + e);   // 1 - sigmoid(x)
    float p   = fmaxf(r, PROB_MIN);
    float omp = 1.0f - p;
    return -(1.0f - ALPHA) * omp * omp * __logf(p);
}
__device__ __forceinline__ float loss_gen(float x, bool gt) {
    float e   = __expf(x);
    float r   = __fdividef(1.0f, 1.0f + e);
    float p   = gt ? (1.0f - r) : r;
    p = fmaxf(p, PROB_MIN);
    float a   = gt ? ALPHA : (1.0f - ALPHA);
    float omp = 1.0f - p;
    return -a * omp * omp * __logf(p);
}

// ---------------------------------------------------------------------------
// Gather + bf16 convert. 4 channels/thread. Half-warp (16 threads) shares one
// (b,k): only the leader lane loads mask+indices, others __shfl them.
// Inline int64/int32 index-dtype detection (JAX x64 ambiguity).
// ---------------------------------------------------------------------------
__global__ __launch_bounds__(256)
void gather_kernel(const float* __restrict__ cur_reid,
                   const float* __restrict__ pre_reid,
                   const void*  __restrict__ cur_inds,
                   const void*  __restrict__ pre_inds,
                   const void*  __restrict__ cur_cir,
                   const void*  __restrict__ pre_cir,
                   const int*   __restrict__ mask)
{
    __shared__ int s64;
    if (threadIdx.x < 32) {
        long long v = ((const long long*)cur_inds)[threadIdx.x];
        unsigned bad = __ballot_sync(0xffffffffu,
                                     (v < 0) || (v >= (long long)HWSZ));
        if (threadIdx.x == 0) s64 = (bad == 0);
    }
    __syncthreads();

    int tid = blockIdx.x * 256 + threadIdx.x;
    if (tid >= BB * KPAD * 16) return;
    int lid = threadIdx.x & 31;
    int c4  = tid & 15;
    int bk  = tid >> 4;
    int b   = bk >> 9;
    int row = bk & (KPAD - 1);

    uint2* dstC = (uint2*)g_curb;
    uint2* dstP = (uint2*)g_preb;

    if (row >= KK) {
        uint2 z = make_uint2(0u, 0u);
        dstC[tid] = z;
        dstP[tid] = z;
        return;
    }

    // Leader lane of each half-warp loads the shared (mask, ic, ip).
    int leader = lid & 16;
    int ic = 0, ip = 0;
    if ((lid & 15) == 0) {
        int mk = b * KK + row;
        int m  = mask[mk];
        if (s64) {
            ic = (int)(m ? ((const long long*)cur_inds)[mk]
                         : ((const long long*)cur_cir)[mk]);
            ip = (int)(m ? ((const long long*)pre_inds)[mk]
                         : ((const long long*)pre_cir)[mk]);
        } else {
            ic = m ? ((const int*)cur_inds)[mk] : ((const int*)cur_cir)[mk];
            ip = m ? ((const int*)pre_inds)[mk] : ((const int*)pre_cir)[mk];
        }
    }
    ic = __shfl_sync(0xffffffffu, ic, leader);
    ip = __shfl_sync(0xffffffffu, ip, leader);

    size_t base = ((size_t)b * CC + 4 * c4) * (size_t)HWSZ;
    float c0 = cur_reid[base + ic];
    float c1 = cur_reid[base + HWSZ + ic];
    float c2 = cur_reid[base + 2 * (size_t)HWSZ + ic];
    float c3 = cur_reid[base + 3 * (size_t)HWSZ + ic];
    float p0 = pre_reid[base + ip];
    float p1 = pre_reid[base + HWSZ + ip];
    float p2 = pre_reid[base + 2 * (size_t)HWSZ + ip];
    float p3 = pre_reid[base + 3 * (size_t)HWSZ + ip];
    __nv_bfloat162 vc0, vc1, vp0, vp1;
    vc0.x = __float2bfloat16(c0); vc0.y = __float2bfloat16(c1);
    vc1.x = __float2bfloat16(c2); vc1.y = __float2bfloat16(c3);
    vp0.x = __float2bfloat16(p0); vp0.y = __float2bfloat16(p1);
    vp1.x = __float2bfloat16(p2); vp1.y = __float2bfloat16(p3);
    uint2 uc, up;
    uc.x = *(uint32_t*)&vc0; uc.y = *(uint32_t*)&vc1;
    up.x = *(uint32_t*)&vp0; up.y = *(uint32_t*)&vp1;
    dstC[tid] = uc;
    dstP[tid] = up;
}

// ---------------------------------------------------------------------------
// HMMA loss kernel (champion round-5 structure): 64x64 tile/block,
// grid (8,8,8)=512 blocks, 8 warps of 32x16 warp tiles.
// B fragments: ONE ldsm_x4 per k-step (lanes 0-15 -> fn0 ch0/ch1,
// lanes 16-31 -> fn1 ch0/ch1) instead of two ldsm_x2.
// ---------------------------------------------------------------------------
__global__ __launch_bounds__(256)
void loss_kernel(const int* __restrict__ mask, float* __restrict__ out)
{
    __shared__ __align__(128) uint8_t smA[64 * 128];
    __shared__ __align__(128) uint8_t smB[64 * 128];
    __shared__ float wsum[8];

    int t   = threadIdx.x;
    int w   = t >> 5;
    int lid = t & 31;
    int b   = blockIdx.z;
    int it  = blockIdx.y;
    int jt  = blockIdx.x;
    int i0  = it * 64;
    int j0  = jt * 64;

    // Stage tiles: 512 x 16B each; swizzle chunk ^= (row & 7).
    const uint4* srcA = (const uint4*)(g_curb + ((size_t)b * KPAD + i0) * CC);
    const uint4* srcB = (const uint4*)(g_preb + ((size_t)b * KPAD + j0) * CC);
    #pragma unroll
    for (int k = 0; k < 2; k++) {
        int u  = t + 256 * k;
        int r  = u >> 3;
        int c  = u & 7;
        int sw = (r << 7) + ((c ^ (r & 7)) << 4);
        *(uint4*)(smA + sw) = srcA[u];
        *(uint4*)(smB + sw) = srcB[u];
    }
    __syncthreads();

    uint32_t baseA = smem_u32(smA);
    uint32_t baseB = smem_u32(smB);

    int wm = w & 1;        // 2 x 32 rows
    int wn = w >> 1;       // 4 x 16 cols

    float acc[2][2][4] = {};
    #pragma unroll
    for (int ks = 0; ks < 4; ks++) {
        int kc = ks * 2;
        uint32_t a[2][4];
        #pragma unroll
        for (int fm = 0; fm < 2; fm++) {
            int row = wm * 32 + fm * 16 + (lid & 7) + ((lid >> 3) & 1) * 8;
            int ch  = kc + (lid >> 4);
            uint32_t addr = baseA + (row << 7) + ((ch ^ (row & 7)) << 4);
            ldsm_x4(a[fm][0], a[fm][1], a[fm][2], a[fm][3], addr);
        }
        // B: one x4 -> {fn0ch0, fn0ch1, fn1ch0, fn1ch1}
        uint32_t bf[2][2];
        {
            int row = wn * 16 + ((lid >> 4) & 1) * 8 + (lid & 7);
            int ch  = kc + ((lid >> 3) & 1);
            uint32_t addr = baseB + (row << 7) + ((ch ^ (row & 7)) << 4);
            ldsm_x4(bf[0][0], bf[0][1], bf[1][0], bf[1][1], addr);
        }
        #pragma unroll
        for (int fm = 0; fm < 2; fm++)
            #pragma unroll
            for (int fn = 0; fn < 2; fn++)
                mma_16816(acc[fm][fn], a[fm], bf[fn]);
    }

    // Epilogue on fragments: c0:(i,j) c1:(i,j+1) c2:(i+8,j) c3:(i+8,j+1)
    int gid = lid >> 2;
    int tig = lid & 3;
    float lsum = 0.0f;

    bool interior = (it < 7) && (jt < 7);
    bool diag     = (it == jt);

    if (interior && !diag) {
        #pragma unroll
        for (int fm = 0; fm < 2; fm++)
            #pragma unroll
            for (int fn = 0; fn < 2; fn++)
                #pragma unroll
                for (int rg = 0; rg < 4; rg++)
                    lsum += loss_fast(acc[fm][fn][rg]);
    } else {
        #pragma unroll
        for (int fm = 0; fm < 2; fm++) {
            int ib = i0 + wm * 32 + fm * 16 + gid;
            int m0 = (diag && ib     < KK) ? mask[b * KK + ib]     : 0;
            int m8 = (diag && ib + 8 < KK) ? mask[b * KK + ib + 8] : 0;
            #pragma unroll
            for (int fn = 0; fn < 2; fn++) {
                int jb = j0 + wn * 16 + fn * 8 + 2 * tig;
                #pragma unroll
                for (int rg = 0; rg < 4; rg++) {
                    int i = ib + (rg >> 1) * 8;
                    int j = jb + (rg & 1);
                    if (i < KK && j < KK) {
                        bool gt = diag && (i == j) &&
                                  (((rg >> 1) ? m8 : m0) != 0);
                        lsum += loss_gen(acc[fm][fn][rg], gt);
                    }
                }
            }
        }
    }

    // Reduce + last-block finalize
    #pragma unroll
    for (int o = 16; o > 0; o >>= 1)
        lsum += __shfl_xor_sync(0xffffffffu, lsum, o);
    if (lid == 0) wsum[w] = lsum;
    __syncthreads();

    if (t == 0) {
        float v = 0.f;
        #pragma unroll
        for (int k = 0; k < 8; k++) v += wsum[k];
        int bid = blockIdx.x + 8 * (blockIdx.y + 8 * blockIdx.z);
        atomicAdd(&g_accs[bid & (NSLOTS - 1)], (double)v);
        __threadfence();
        unsigned old = atomicAdd(&g_count, 1u);
        if (old == NLBLK - 1) {           // last block: finalize + reset
            double tot = 0.0;
            #pragma unroll
            for (int s = 0; s < NSLOTS; s++) {
                tot += g_accs[s];
                g_accs[s] = 0.0;
            }
            out[0] = (float)(tot / ((double)BB * KK * KK));
            __threadfence();
            g_count = 0u;
        }
    }
}

extern "C" void kernel_launch(void* const* d_in, const int* in_sizes, int n_in,
                              void* d_out, int out_size)
{
    const float* cur_reid = (const float*)d_in[0];
    const float* pre_reid = (const float*)d_in[1];
    const int*   mask     = (const int*)d_in[6];
    float* out = (float*)d_out;

    int totalGroups = BB * KPAD * 16;
    gather_kernel<<<(totalGroups + 255) / 256, 256>>>(cur_reid, pre_reid,
                                                      d_in[2], d_in[3],
                                                      d_in[4], d_in[5], mask);

    dim3 grid(8, 8, BB);
    loss_kernel<<<grid, 256>>>(mask, out);
}

// round 13
// speedup vs baseline: 1.4310x; 1.1379x over previous
#include <cuda_runtime.h>
#include <cuda_bf16.h>
#include <cstdint>

#define BB 8
#define CC 64
#define HWSZ (152 * 272)     // 41344
#define KK 500
#define KPAD 512
#define NSLOTS 128

#define ALPHA 0.25f
#define PROB_MIN 1e-4f

// Scratch (no allocations allowed)
__device__ __align__(16) __nv_bfloat16 g_curb[BB * KPAD * CC];
__device__ __align__(16) __nv_bfloat16 g_preb[BB * KPAD * CC];
__device__ double g_accs[NSLOTS];   // zero-init; finalize resets after reading

__device__ __forceinline__ uint32_t smem_u32(const void* p) {
    uint32_t a;
    asm("{ .reg .u64 t; cvta.to.shared.u64 t, %1; cvt.u32.u64 %0, t; }"
        : "=r"(a) : "l"(p));
    return a;
}
__device__ __forceinline__ void ldsm_x4(uint32_t& r0, uint32_t& r1,
                                        uint32_t& r2, uint32_t& r3,
                                        uint32_t addr) {
    asm volatile("ldmatrix.sync.aligned.m8n8.x4.shared.b16 {%0,%1,%2,%3}, [%4];"
                 : "=r"(r0), "=r"(r1), "=r"(r2), "=r"(r3) : "r"(addr));
}
__device__ __forceinline__ void ldsm_x2(uint32_t& r0, uint32_t& r1,
                                        uint32_t addr) {
    asm volatile("ldmatrix.sync.aligned.m8n8.x2.shared.b16 {%0,%1}, [%2];"
                 : "=r"(r0), "=r"(r1) : "r"(addr));
}
__device__ __forceinline__ void mma_16816(float* c, const uint32_t* a,
                                          const uint32_t* b) {
    asm volatile(
        "mma.sync.aligned.m16n8k16.row.col.f32.bf16.bf16.f32 "
        "{%0,%1,%2,%3}, {%4,%5,%6,%7}, {%8,%9}, {%0,%1,%2,%3};"
        : "+f"(c[0]), "+f"(c[1]), "+f"(c[2]), "+f"(c[3])
        : "r"(a[0]), "r"(a[1]), "r"(a[2]), "r"(a[3]), "r"(b[0]), "r"(b[1]));
}

// ---------------------------------------------------------------------------
// Gather + bf16 convert (identical to the proven round-7 version).
// ---------------------------------------------------------------------------
__global__ __launch_bounds__(256)
void gather_kernel(const float* __restrict__ cur_reid,
                   const float* __restrict__ pre_reid,
                   const void*  __restrict__ cur_inds,
                   const void*  __restrict__ pre_inds,
                   const void*  __restrict__ cur_cir,
                   const void*  __restrict__ pre_cir,
                   const int*   __restrict__ mask)
{
    __shared__ int s64;
    if (threadIdx.x < 32) {
        long long v = ((const long long*)cur_inds)[threadIdx.x];
        unsigned bad = __ballot_sync(0xffffffffu,
                                     (v < 0) || (v >= (long long)HWSZ));
        if (threadIdx.x == 0) s64 = (bad == 0);
    }
    __syncthreads();

    int tid = blockIdx.x * 256 + threadIdx.x;
    if (tid >= BB * KPAD * 16) return;
    int c4  = tid & 15;
    int bk  = tid >> 4;
    int b   = bk >> 9;
    int row = bk & (KPAD - 1);

    uint2* dstC = (uint2*)g_curb;
    uint2* dstP = (uint2*)g_preb;

    if (row >= KK) {
        uint2 z = make_uint2(0u, 0u);
        dstC[tid] = z;
        dstP[tid] = z;
        return;
    }
    int mk = b * KK + row;
    int m  = mask[mk];
    int ic, ip;
    if (s64) {
        ic = (int)(m ? ((const long long*)cur_inds)[mk]
                     : ((const long long*)cur_cir)[mk]);
        ip = (int)(m ? ((const long long*)pre_inds)[mk]
                     : ((const long long*)pre_cir)[mk]);
    } else {
        ic = m ? ((const int*)cur_inds)[mk] : ((const int*)cur_cir)[mk];
        ip = m ? ((const int*)pre_inds)[mk] : ((const int*)pre_cir)[mk];
    }
    size_t base = ((size_t)b * CC + 4 * c4) * (size_t)HWSZ;
    float c0 = cur_reid[base + ic];
    float c1 = cur_reid[base + HWSZ + ic];
    float c2 = cur_reid[base + 2 * (size_t)HWSZ + ic];
    float c3 = cur_reid[base + 3 * (size_t)HWSZ + ic];
    float p0 = pre_reid[base + ip];
    float p1 = pre_reid[base + HWSZ + ip];
    float p2 = pre_reid[base + 2 * (size_t)HWSZ + ip];
    float p3 = pre_reid[base + 3 * (size_t)HWSZ + ip];
    __nv_bfloat162 vc0, vc1, vp0, vp1;
    vc0.x = __float2bfloat16(c0); vc0.y = __float2bfloat16(c1);
    vc1.x = __float2bfloat16(c2); vc1.y = __float2bfloat16(c3);
    vp0.x = __float2bfloat16(p0); vp0.y = __float2bfloat16(p1);
    vp1.x = __float2bfloat16(p2); vp1.y = __float2bfloat16(p3);
    uint2 uc, up;
    uc.x = *(uint32_t*)&vc0; uc.y = *(uint32_t*)&vc1;
    up.x = *(uint32_t*)&vp0; up.y = *(uint32_t*)&vp1;
    dstC[tid] = uc;
    dstP[tid] = up;
}

// ---------------------------------------------------------------------------
// HMMA loss kernel (round-7 champion structure), with the epilogue rewritten
// BREADTH-FIRST: all 16 expf, then all 16 rcp, then all 16 logf — so the 16
// independent MUFU chains overlap instead of serializing at low reg budget.
// ---------------------------------------------------------------------------
__global__ __launch_bounds__(256)
void loss_kernel(const int* __restrict__ mask)
{
    __shared__ __align__(128) uint8_t smA[64 * 128];
    __shared__ __align__(128) uint8_t smB[64 * 128];
    __shared__ float wsum[8];

    int t   = threadIdx.x;
    int w   = t >> 5;
    int lid = t & 31;
    int b   = blockIdx.z;
    int it  = blockIdx.y;
    int jt  = blockIdx.x;
    int i0  = it * 64;
    int j0  = jt * 64;

    const uint4* srcA = (const uint4*)(g_curb + ((size_t)b * KPAD + i0) * CC);
    const uint4* srcB = (const uint4*)(g_preb + ((size_t)b * KPAD + j0) * CC);
    #pragma unroll
    for (int k = 0; k < 2; k++) {
        int u  = t + 256 * k;
        int r  = u >> 3;
        int c  = u & 7;
        int sw = (r << 7) + ((c ^ (r & 7)) << 4);
        *(uint4*)(smA + sw) = srcA[u];
        *(uint4*)(smB + sw) = srcB[u];
    }
    __syncthreads();

    uint32_t baseA = smem_u32(smA);
    uint32_t baseB = smem_u32(smB);

    int wm = w & 1;
    int wn = w >> 1;

    float acc[2][2][4] = {};
    #pragma unroll
    for (int ks = 0; ks < 4; ks++) {
        int kc = ks * 2;
        uint32_t a[2][4];
        #pragma unroll
        for (int fm = 0; fm < 2; fm++) {
            int row = wm * 32 + fm * 16 + (lid & 7) + ((lid >> 3) & 1) * 8;
            int ch  = kc + (lid >> 4);
            uint32_t addr = baseA + (row << 7) + ((ch ^ (row & 7)) << 4);
            ldsm_x4(a[fm][0], a[fm][1], a[fm][2], a[fm][3], addr);
        }
        uint32_t bf[2][2];
        #pragma unroll
        for (int fn = 0; fn < 2; fn++) {
            int l8  = lid & 15;
            int row = wn * 16 + fn * 8 + (l8 & 7);
            int ch  = kc + (l8 >> 3);
            uint32_t addr = baseB + (row << 7) + ((ch ^ (row & 7)) << 4);
            ldsm_x2(bf[fn][0], bf[fn][1], addr);
        }
        #pragma unroll
        for (int fm = 0; fm < 2; fm++)
            #pragma unroll
            for (int fn = 0; fn < 2; fn++)
                mma_16816(acc[fm][fn], a[fm], bf[fn]);
    }

    // ---------------- breadth-first epilogue ----------------
    int gid = lid >> 2;
    int tig = lid & 3;
    float lsum = 0.0f;

    bool interior = (it < 7) && (jt < 7);
    bool diag     = (it == jt);

    float xs[16];
    #pragma unroll
    for (int fm = 0; fm < 2; fm++)
        #pragma unroll
        for (int fn = 0; fn < 2; fn++)
            #pragma unroll
            for (int rg = 0; rg < 4; rg++)
                xs[fm * 8 + fn * 4 + rg] = acc[fm][fn][rg];

    if (interior && !diag) {
        float u[16], pc[16], lg[16];
        #pragma unroll
        for (int i = 0; i < 16; i++) u[i] = __expf(xs[i]);
        #pragma unroll
        for (int i = 0; i < 16; i++)
            pc[i] = fmaxf(__fdividef(1.0f, 1.0f + u[i]), PROB_MIN);
        #pragma unroll
        for (int i = 0; i < 16; i++) lg[i] = __logf(pc[i]);
        #pragma unroll
        for (int i = 0; i < 16; i++) {
            float omp = 1.0f - pc[i];
            lsum -= (1.0f - ALPHA) * omp * omp * lg[i];
        }
    } else {
        float wgt[16];
        bool  flip[16];
        #pragma unroll
        for (int fm = 0; fm < 2; fm++) {
            int ib = i0 + wm * 32 + fm * 16 + gid;
            int m0 = (diag && ib     < KK) ? mask[b * KK + ib]     : 0;
            int m8 = (diag && ib + 8 < KK) ? mask[b * KK + ib + 8] : 0;
            #pragma unroll
            for (int fn = 0; fn < 2; fn++) {
                int jb = j0 + wn * 16 + fn * 8 + 2 * tig;
                #pragma unroll
                for (int rg = 0; rg < 4; rg++) {
                    int i = ib + (rg >> 1) * 8;
                    int j = jb + (rg & 1);
                    int idx = fm * 8 + fn * 4 + rg;
                    bool inb = (i < KK) && (j < KK);
                    bool gt  = diag && (i == j) &&
                               (((rg >> 1) ? m8 : m0) != 0);
                    flip[idx] = gt;
                    wgt[idx]  = inb ? (gt ? ALPHA : (1.0f - ALPHA)) : 0.0f;
                }
            }
        }
        float u[16], pc[16], lg[16];
        #pragma unroll
        for (int i = 0; i < 16; i++) u[i] = __expf(xs[i]);
        #pragma unroll
        for (int i = 0; i < 16; i++) {
            float r = __fdividef(1.0f, 1.0f + u[i]);
            pc[i] = fmaxf(flip[i] ? (1.0f - r) : r, PROB_MIN);
        }
        #pragma unroll
        for (int i = 0; i < 16; i++) lg[i] = __logf(pc[i]);
        #pragma unroll
        for (int i = 0; i < 16; i++) {
            float omp = 1.0f - pc[i];
            lsum -= wgt[i] * omp * omp * lg[i];
        }
    }

    // Reduce -> spread slot (round-7 proven)
    #pragma unroll
    for (int o = 16; o > 0; o >>= 1)
        lsum += __shfl_xor_sync(0xffffffffu, lsum, o);
    if (lid == 0) wsum[w] = lsum;
    __syncthreads();

    if (t == 0) {
        float v = 0.f;
        #pragma unroll
        for (int k = 0; k < 8; k++) v += wsum[k];
        int bid = blockIdx.x + 8 * blockIdx.y + 64 * blockIdx.z;
        atomicAdd(&g_accs[bid & (NSLOTS - 1)], (double)v);
    }
}

// ---------------------------------------------------------------------------
// Finalize: sum the slots, write mean, reset slots (graph-replay safe).
// ---------------------------------------------------------------------------
__global__ void finalize_kernel(float* __restrict__ out)
{
    __shared__ double ssum[4];
    int t = threadIdx.x;          // 128 threads
    double v = g_accs[t];
    g_accs[t] = 0.0;
    #pragma unroll
    for (int o = 16; o > 0; o >>= 1)
        v += __shfl_xor_sync(0xffffffffu, v, o);
    if ((t & 31) == 0) ssum[t >> 5] = v;
    __syncthreads();
    if (t == 0) {
        double tot = ssum[0] + ssum[1] + ssum[2] + ssum[3];
        out[0] = (float)(tot / ((double)BB * KK * KK));
    }
}

extern "C" void kernel_launch(void* const* d_in, const int* in_sizes, int n_in,
                              void* d_out, int out_size)
{
    const float* cur_reid = (const float*)d_in[0];
    const float* pre_reid = (const float*)d_in[1];
    const int*   mask     = (const int*)d_in[6];
    float* out = (float*)d_out;

    int totalGroups = BB * KPAD * 16;
    gather_kernel<<<(totalGroups + 255) / 256, 256>>>(cur_reid, pre_reid,
                                                      d_in[2], d_in[3],
                                                      d_in[4], d_in[5], mask);

    dim3 grid(8, 8, BB);
    loss_kernel<<<grid, 256>>>(mask);

    finalize_kernel<<<1, 128>>>(out);
}